// round 10
// baseline (speedup 1.0000x reference)
#include <cuda_runtime.h>
#include <math.h>
#include <stdint.h>

#define HIDDEN   2048
#define HEADS    16
#define HEAD_DIM 128
#define BATCH    2
#define SEQ      1024
#define MROWS    (BATCH*SEQ)

// ---------------- scratch (allocation-free: device globals) ----------------
__device__ float g_q[BATCH*HEADS*SEQ*HEAD_DIM];
__device__ float g_k[BATCH*HEADS*SEQ*HEAD_DIM];
__device__ float g_v[BATCH*HEADS*SEQ*HEAD_DIM];
__device__ float g_attn[MROWS*HIDDEN];
__device__ float g_xc[MROWS*HIDDEN];        // tf32-rounded x
__device__ float g_wt[4*HIDDEN*HIDDEN];     // tf32-rounded transposed weights [N,K]

// ============================================================================
// helpers
// ============================================================================
__device__ __forceinline__ uint32_t smem_u32(const void* p) {
    uint32_t a;
    asm("{ .reg .u64 t; cvta.to.shared.u64 t, %1; cvt.u32.u64 %0, t; }"
        : "=r"(a) : "l"(p));
    return a;
}
__device__ __forceinline__ float to_tf32(float x) {
    uint32_t u;
    asm("cvt.rna.tf32.f32 %0, %1;" : "=r"(u) : "f"(x));
    return __uint_as_float(u);
}
__device__ __forceinline__ void cpa16(uint32_t s, const void* g) {
    asm volatile("cp.async.cg.shared.global [%0], [%1], 16;" :: "r"(s), "l"(g));
}
#define CPA_COMMIT() asm volatile("cp.async.commit_group;" ::: "memory")
template<int N> __device__ __forceinline__ void cpa_wait() {
    asm volatile("cp.async.wait_group %0;" :: "n"(N) : "memory");
}
__device__ __forceinline__ void mma16n8k8(float* c, const uint32_t* a, const uint32_t* b) {
    asm volatile(
        "mma.sync.aligned.m16n8k8.row.col.f32.tf32.tf32.f32 "
        "{%0,%1,%2,%3}, {%4,%5,%6,%7}, {%8,%9}, {%0,%1,%2,%3};"
        : "+f"(c[0]), "+f"(c[1]), "+f"(c[2]), "+f"(c[3])
        : "r"(a[0]), "r"(a[1]), "r"(a[2]), "r"(a[3]), "r"(b[0]), "r"(b[1]));
}

// 2^x via FMA-pipe polynomial (no MUFU)
__device__ __forceinline__ float exp2c(float x) {
    x = fmaxf(x, -126.f);
    float fl = floorf(x);
    float f  = x - fl;
    int   i  = (int)fl;
    float r = 1.52527338e-5f;
    r = fmaf(r, f, 1.54035304e-4f);
    r = fmaf(r, f, 1.33335581e-3f);
    r = fmaf(r, f, 9.61812911e-3f);
    r = fmaf(r, f, 5.55041087e-2f);
    r = fmaf(r, f, 2.40226507e-1f);
    r = fmaf(r, f, 6.93147181e-1f);
    r = fmaf(r, f, 1.0f);
    return r * __int_as_float((i + 127) << 23);
}
// log2(1+u) for u in [0, ~0.101]
__device__ __forceinline__ float log2p_small(float u) {
    float r = 0.14285714f;
    r = fmaf(r, u, -0.16666667f);
    r = fmaf(r, u, 0.2f);
    r = fmaf(r, u, -0.25f);
    r = fmaf(r, u, 0.33333333f);
    r = fmaf(r, u, -0.5f);
    r = fmaf(r, u, 1.0f);
    return r * u * 1.4426950408889634f;
}

// ============================================================================
// K0a: weight transpose + tf32 round: W[K,N] -> Wt[N,K], 4 matrices (z-grid)
// ============================================================================
__global__ void transpose2048(const float* __restrict__ s0, const float* __restrict__ s1,
                              const float* __restrict__ s2, const float* __restrict__ s3,
                              float* __restrict__ dst)
{
    __shared__ float tile[32][33];
    int z = blockIdx.z;
    const float* src = (z == 0) ? s0 : (z == 1) ? s1 : (z == 2) ? s2 : s3;
    float* d = dst + (size_t)z * HIDDEN * HIDDEN;
    int tx = threadIdx.x & 31, ty = threadIdx.x >> 5;
    int x  = blockIdx.x * 32 + tx, y0 = blockIdx.y * 32 + ty;
#pragma unroll
    for (int j = 0; j < 4; ++j)
        tile[ty + j * 8][tx] = to_tf32(src[(size_t)(y0 + j * 8) * HIDDEN + x]);
    __syncthreads();
    int x2 = blockIdx.y * 32 + tx, y2 = blockIdx.x * 32 + ty;
#pragma unroll
    for (int j = 0; j < 4; ++j)
        d[(size_t)(y2 + j * 8) * HIDDEN + x2] = tile[tx][ty + j * 8];
}

// ============================================================================
// K0b: elementwise tf32 rounding (x only)
// ============================================================================
__global__ void cvt_tf32_kernel(const float* __restrict__ src, float* __restrict__ dst, int n4)
{
    int i = blockIdx.x * blockDim.x + threadIdx.x;
    if (i >= n4) return;
    float4 v = ((const float4*)src)[i];
    v.x = to_tf32(v.x); v.y = to_tf32(v.y); v.z = to_tf32(v.z); v.w = to_tf32(v.w);
    ((float4*)dst)[i] = v;
}

// ============================================================================
// K1/K4: tf32 mma.sync GEMM (unchanged from R9)
// ============================================================================
#define BM 128
#define BN 128
#define BK 32
#define PADK 40
#define ASTAGE (BM*PADK)
#define BSTAGE (BN*PADK)
#define NKT (HIDDEN / BK)
#define STAGE_FLOATS (ASTAGE + BSTAGE)
#define NSTAGE 2
#define GEMM_SMEM (NSTAGE * STAGE_FLOATS * 4)

__global__ __launch_bounds__(128, 2) void gemm_mma_kernel(
    const float* __restrict__ A,
    const float* __restrict__ B0, const float* __restrict__ B1, const float* __restrict__ B2,
    float* __restrict__ D0, float* __restrict__ D1, float* __restrict__ D2,
    const float* __restrict__ bias, int mode)
{
    extern __shared__ float sm[];
    const int t    = threadIdx.x;
    const int wid  = t >> 5;
    const int lane = t & 31;
    const int gid  = lane >> 2;
    const int tig  = lane & 3;
    const int z = blockIdx.z;
    const float* __restrict__ B = (z == 0) ? B0 : (z == 1) ? B1 : B2;
    float* __restrict__ D       = (z == 0) ? D0 : (z == 1) ? D1 : D2;
    const int n0 = blockIdx.x * BN;
    const int m0 = blockIdx.y * BM;
    const int wm = (wid & 1) * 64;
    const int wn = (wid >> 1) * 64;

    const uint32_t smb = smem_u32(sm);

    const int ar = t >> 3;
    const int ac = (t & 7) * 4;
    const float* agp = A + (size_t)(m0 + ar) * HIDDEN + ac;
    const float* bgp = B + (size_t)(n0 + ar) * HIDDEN + ac;
    const uint32_t asb = smb + (uint32_t)(ar * PADK + ac) * 4;
    const uint32_t bsb = smb + (uint32_t)(ASTAGE + ar * PADK + ac) * 4;

    float acc[4][8][4];
#pragma unroll
    for (int mi = 0; mi < 4; ++mi)
#pragma unroll
        for (int ni = 0; ni < 8; ++ni)
#pragma unroll
            for (int j = 0; j < 4; ++j) acc[mi][ni][j] = 0.f;

    auto issue = [&](int kt, int s) {
        const uint32_t so = (uint32_t)(s * STAGE_FLOATS) * 4;
        const int ko = kt * BK;
#pragma unroll
        for (int i = 0; i < 8; ++i)
            cpa16(asb + so + (uint32_t)(i * 16 * PADK) * 4, agp + (size_t)i * 16 * HIDDEN + ko);
#pragma unroll
        for (int i = 0; i < 8; ++i)
            cpa16(bsb + so + (uint32_t)(i * 16 * PADK) * 4, bgp + (size_t)i * 16 * HIDDEN + ko);
        CPA_COMMIT();
    };

    issue(0, 0);

    for (int kt = 0; kt < NKT; ++kt) {
        cpa_wait<0>();
        __syncthreads();
        if (kt + 1 < NKT) issue(kt + 1, (kt + 1) & 1);

        const float* As = sm + (kt & 1) * STAGE_FLOATS;
        const float* Bs = As + ASTAGE;

#pragma unroll
        for (int ks = 0; ks < 4; ++ks) {
            const int kk = ks * 8 + 2 * tig;
            uint32_t a[4][4], b[8][2];
#pragma unroll
            for (int mi = 0; mi < 4; ++mi) {
                const int r = wm + mi * 16 + gid;
                uint2 v0 = *(const uint2*)&As[r * PADK + kk];
                uint2 v1 = *(const uint2*)&As[(r + 8) * PADK + kk];
                a[mi][0] = v0.x; a[mi][2] = v0.y;
                a[mi][1] = v1.x; a[mi][3] = v1.y;
            }
#pragma unroll
            for (int ni = 0; ni < 8; ++ni) {
                const int c = wn + ni * 8 + gid;
                uint2 v = *(const uint2*)&Bs[c * PADK + kk];
                b[ni][0] = v.x; b[ni][1] = v.y;
            }
#pragma unroll
            for (int mi = 0; mi < 4; ++mi)
#pragma unroll
                for (int ni = 0; ni < 8; ++ni)
                    mma16n8k8(acc[mi][ni], a[mi], b[ni]);
        }
    }

#pragma unroll
    for (int mi = 0; mi < 4; ++mi) {
#pragma unroll
        for (int ni = 0; ni < 8; ++ni) {
            const int c = wn + ni * 8 + 2 * tig;
            const int r0 = wm + mi * 16 + gid;
            const int r1 = r0 + 8;
            float2 v0 = {acc[mi][ni][0], acc[mi][ni][1]};
            float2 v1 = {acc[mi][ni][2], acc[mi][ni][3]};
            if (mode == 0) {
                float2 bb = *(const float2*)&bias[n0 + c];
                v0.x += bb.x; v0.y += bb.y;
                v1.x += bb.x; v1.y += bb.y;
                *(float2*)&D[(size_t)(m0 + r0) * HIDDEN + n0 + c] = v0;
                *(float2*)&D[(size_t)(m0 + r1) * HIDDEN + n0 + c] = v1;
            } else {
                const int h = blockIdx.x;
                int m = m0 + r0;
                int bb0 = m >> 10, s0q = m & 1023;
                *(float2*)&D[(((size_t)(bb0 * HEADS + h) * SEQ + s0q) << 7) + c] = v0;
                m = m0 + r1;
                int bb1 = m >> 10, s1q = m & 1023;
                *(float2*)&D[(((size_t)(bb1 * HEADS + h) * SEQ + s1q) << 7) + c] = v1;
            }
        }
    }
}

// ============================================================================
// K2: RoPE in place on q,k; k,v rounded to tf32
// ============================================================================
__global__ void rope_kernel(float* __restrict__ q, float* __restrict__ k, float* __restrict__ v)
{
    int idx = blockIdx.x * blockDim.x + threadIdx.x;
    if (idx >= BATCH * HEADS * SEQ * 64) return;
    int i  = idx & 63;
    int s  = (idx >> 6) & (SEQ - 1);
    int bh = idx >> 16;

    float inv = expf(-(float)(2 * i) * (9.210340371976184f / 128.f));
    float th  = (float)s * inv;
    float sn, cs;
    sincosf(th, &sn, &cs);

    size_t base = ((size_t)bh * SEQ + s) * HEAD_DIM + i;
    float q1 = q[base], q2 = q[base + 64];
    q[base]      = q1 * cs - q2 * sn;
    q[base + 64] = q2 * cs + q1 * sn;
    float k1 = k[base], k2 = k[base + 64];
    k[base]      = to_tf32(k1 * cs - k2 * sn);
    k[base + 64] = to_tf32(k2 * cs + k1 * sn);
    v[base]      = to_tf32(v[base]);
    v[base + 64] = to_tf32(v[base + 64]);
}

// ============================================================================
// K3: causal flash attention — register-resident P.
// 256 threads, 8 warps (4m x 2n). Each warp: 16 q-rows x 32 S-cols (QK), and
// PV over its own 32 S-cols for ALL 128 dims (per-warp partial O in regs).
// P stays in registers (k-slice-permuted A fragment). 2 barriers per KV tile.
// Per-thread m; per-warp partial l; O and l reduced across the 2 n-warps once.
// ============================================================================
#define FPADD 136
#define FPADV 132
#define OQH  0
#define OQL  8704
#define OKS  17408              // 2 stages x 8704
#define OVS  34816              // 2 stages x 8448
#define OSLAB OKS               // epilogue reuse: 64 x 136 partial O
#define ORDM 51712              // 2 x 64 per-warp row maxes
#define ORDL 51840              // 64 partial l
#define FLASH_FLOATS 51904
#define FLASH_SMEM (FLASH_FLOATS * 4)

__global__ __launch_bounds__(256, 1) void flash_kernel(
    const float* __restrict__ q, const float* __restrict__ k, const float* __restrict__ v,
    const float* __restrict__ pm, const float* __restrict__ pol, const float* __restrict__ mw,
    float* __restrict__ attn)
{
    extern __shared__ float smf[];
    const uint32_t smb = smem_u32(smf);

    const int t    = threadIdx.x;
    const int wid  = t >> 5;
    const int lane = t & 31;
    const int gid  = lane >> 2;
    const int tig  = lane & 3;
    const int wm   = (wid & 3) * 16;
    const int wni  = wid >> 2;           // 0/1
    const int wn   = wni * 32;           // warp's S-col base

    const int qt = (gridDim.x - 1) - blockIdx.x;
    const int bh = blockIdx.y;
    const int q0 = qt * 64;

    const float* qb = q + (size_t)bh * SEQ * HEAD_DIM;
    const float* kb = k + (size_t)bh * SEQ * HEAD_DIM;
    const float* vb = v + (size_t)bh * SEQ * HEAD_DIM;
    const size_t moff = (size_t)bh * SEQ * SEQ;

    // ---- load Q tile, split hi/lo tf32 ----
    for (int idx = t; idx < 64 * 32; idx += 256) {
        int r  = idx >> 5;
        int c4 = (idx & 31) * 4;
        float4 x = *(const float4*)&qb[(size_t)(q0 + r) * HEAD_DIM + c4];
        float* qh = smf + OQH + r * FPADD + c4;
        float* ql = smf + OQL + r * FPADD + c4;
        float h0 = to_tf32(x.x); qh[0] = h0; ql[0] = to_tf32(x.x - h0);
        float h1 = to_tf32(x.y); qh[1] = h1; ql[1] = to_tf32(x.y - h1);
        float h2 = to_tf32(x.z); qh[2] = h2; ql[2] = to_tf32(x.z - h2);
        float h3 = to_tf32(x.w); qh[3] = h3; ql[3] = to_tf32(x.w - h3);
    }

    auto issueKV = [&](int jt, int s) {
        const int j0 = jt * 64;
#pragma unroll
        for (int i = 0; i < 8; ++i) {
            int idx = i * 256 + t;
            int r  = idx >> 5;
            int c4 = (idx & 31) * 4;
            cpa16(smb + (uint32_t)(OKS + s * 8704 + r * FPADD + c4) * 4,
                  &kb[(size_t)(j0 + r) * HEAD_DIM + c4]);
            cpa16(smb + (uint32_t)(OVS + s * 8448 + r * FPADV + c4) * 4,
                  &vb[(size_t)(j0 + r) * HEAD_DIM + c4]);
        }
        CPA_COMMIT();
    };

    issueKV(0, 0);

    const float SC2  = 0.08838834764831845f * 1.4426950408889634f;
    const float CPM  = 0.05f * 1.4426950408889634f;
    const float CPO  = 0.1f  * 1.4426950408889634f;

    const int row0  = wm + gid;
    const int row1  = row0 + 8;
    const int grow0 = q0 + row0;
    const int grow1 = q0 + row1;

    float m0 = -1e30f, m1 = -1e30f;      // per-thread running max (log2 domain)
    float l0 = 0.f,    l1 = 0.f;         // per-warp partial l (own S-cols)
    float acc_o[16][4];                  // partial O: all 128 dims, own S-cols
#pragma unroll
    for (int nd = 0; nd < 16; ++nd)
#pragma unroll
        for (int j = 0; j < 4; ++j) acc_o[nd][j] = 0.f;

    for (int jt = 0; jt <= qt; ++jt) {
        cpa_wait<0>();
        __syncthreads();   // #1: KV stage jt ready; prev iteration fully done
        if (jt < qt) issueKV(jt + 1, (jt + 1) & 1);

        const float* Kb = smf + OKS + (jt & 1) * 8704;
        const float* Vb = smf + OVS + (jt & 1) * 8448;
        const int j0c = jt * 64;

        // mask prefetch (overlaps QK mma)
        const size_t mr0 = moff + (size_t)grow0 * SEQ + j0c;
        const size_t mr1 = moff + (size_t)grow1 * SEQ + j0c;
        float2 pa0[4], pb0[4], pc0[4], pa1[4], pb1[4], pc1[4];
#pragma unroll
        for (int ni = 0; ni < 4; ++ni) {
            const int cl = wn + ni * 8 + 2 * tig;
            pa0[ni] = *(const float2*)&pm[mr0 + cl];
            pb0[ni] = *(const float2*)&pol[mr0 + cl];
            pc0[ni] = *(const float2*)&mw[mr0 + cl];
            pa1[ni] = *(const float2*)&pm[mr1 + cl];
            pb1[ni] = *(const float2*)&pol[mr1 + cl];
            pc1[ni] = *(const float2*)&mw[mr1 + cl];
        }

        // ---- QK^T (split-Q, LDS.64 slice-permuted) ----
        float accs[4][4];
#pragma unroll
        for (int ni = 0; ni < 4; ++ni)
#pragma unroll
            for (int j = 0; j < 4; ++j) accs[ni][j] = 0.f;

#pragma unroll
        for (int ks = 0; ks < 16; ++ks) {
            const int kk = ks * 8 + 2 * tig;
            uint32_t ah[4], al4[4], b[4][2];
            uint2 h0 = *(const uint2*)&smf[OQH + row0 * FPADD + kk];
            uint2 h1 = *(const uint2*)&smf[OQH + row1 * FPADD + kk];
            uint2 lo0 = *(const uint2*)&smf[OQL + row0 * FPADD + kk];
            uint2 lo1 = *(const uint2*)&smf[OQL + row1 * FPADD + kk];
            ah[0] = h0.x; ah[2] = h0.y; ah[1] = h1.x; ah[3] = h1.y;
            al4[0] = lo0.x; al4[2] = lo0.y; al4[1] = lo1.x; al4[3] = lo1.y;
#pragma unroll
            for (int ni = 0; ni < 4; ++ni) {
                const int c = wn + ni * 8 + gid;
                uint2 bv = *(const uint2*)&Kb[c * FPADD + kk];
                b[ni][0] = bv.x; b[ni][1] = bv.y;
            }
#pragma unroll
            for (int ni = 0; ni < 4; ++ni) {
                mma16n8k8(accs[ni], ah, b[ni]);
                mma16n8k8(accs[ni], al4, b[ni]);
            }
        }

        // ---- bias + causal + tile max ----
        const bool diag = (jt == qt);
        float ml0 = -1e30f, ml1 = -1e30f;
#pragma unroll
        for (int ni = 0; ni < 4; ++ni) {
            const int cl = wn + ni * 8 + 2 * tig;
            float s0 = fmaf(accs[ni][0], SC2, fmaf(pa0[ni].x, CPM, fmaf(pb0[ni].x, CPO, log2p_small(fmaf(pc0[ni].x, 0.1f, 1e-8f)))));
            float s1 = fmaf(accs[ni][1], SC2, fmaf(pa0[ni].y, CPM, fmaf(pb0[ni].y, CPO, log2p_small(fmaf(pc0[ni].y, 0.1f, 1e-8f)))));
            float s2 = fmaf(accs[ni][2], SC2, fmaf(pa1[ni].x, CPM, fmaf(pb1[ni].x, CPO, log2p_small(fmaf(pc1[ni].x, 0.1f, 1e-8f)))));
            float s3 = fmaf(accs[ni][3], SC2, fmaf(pa1[ni].y, CPM, fmaf(pb1[ni].y, CPO, log2p_small(fmaf(pc1[ni].y, 0.1f, 1e-8f)))));
            if (diag) {
                if (cl     > row0) s0 = -1e30f;
                if (cl + 1 > row0) s1 = -1e30f;
                if (cl     > row1) s2 = -1e30f;
                if (cl + 1 > row1) s3 = -1e30f;
            }
            accs[ni][0] = s0; accs[ni][1] = s1; accs[ni][2] = s2; accs[ni][3] = s3;
            ml0 = fmaxf(ml0, fmaxf(s0, s1));
            ml1 = fmaxf(ml1, fmaxf(s2, s3));
        }
#pragma unroll
        for (int o = 1; o < 4; o <<= 1) {
            ml0 = fmaxf(ml0, __shfl_xor_sync(0xffffffffu, ml0, o));
            ml1 = fmaxf(ml1, __shfl_xor_sync(0xffffffffu, ml1, o));
        }
        if (tig == 0) {
            smf[ORDM + wni * 64 + row0] = ml0;
            smf[ORDM + wni * 64 + row1] = ml1;
        }
        __syncthreads();   // #2: cross-warp maxes visible

        float mn0 = fmaxf(m0, fmaxf(smf[ORDM + row0], smf[ORDM + 64 + row0]));
        float mn1 = fmaxf(m1, fmaxf(smf[ORDM + row1], smf[ORDM + 64 + row1]));
        float al0 = exp2c(m0 - mn0);
        float al1 = exp2c(m1 - mn1);
        m0 = mn0; m1 = mn1;

        // ---- p = exp2(s - m), in registers (tf32-rounded) ----
        float sum0 = 0.f, sum1 = 0.f;
#pragma unroll
        for (int ni = 0; ni < 4; ++ni) {
            float p0 = exp2c(accs[ni][0] - mn0);
            float p1 = exp2c(accs[ni][1] - mn0);
            float p2 = exp2c(accs[ni][2] - mn1);
            float p3 = exp2c(accs[ni][3] - mn1);
            sum0 += p0 + p1;
            sum1 += p2 + p3;
            accs[ni][0] = to_tf32(p0);
            accs[ni][1] = to_tf32(p1);
            accs[ni][2] = to_tf32(p2);
            accs[ni][3] = to_tf32(p3);
        }
#pragma unroll
        for (int o = 1; o < 4; o <<= 1) {
            sum0 += __shfl_xor_sync(0xffffffffu, sum0, o);
            sum1 += __shfl_xor_sync(0xffffffffu, sum1, o);
        }
        l0 = l0 * al0 + sum0;
        l1 = l1 * al1 + sum1;

        // rescale partial O
#pragma unroll
        for (int nd = 0; nd < 16; ++nd) {
            acc_o[nd][0] *= al0; acc_o[nd][1] *= al0;
            acc_o[nd][2] *= al1; acc_o[nd][3] *= al1;
        }

        // ---- P·V straight from registers (k-slice permuted) ----
#pragma unroll
        for (int ni = 0; ni < 4; ++ni) {
            // A fragment: slice tig <-> col 2tig, slice tig+4 <-> col 2tig+1
            uint32_t a[4];
            a[0] = __float_as_uint(accs[ni][0]);
            a[1] = __float_as_uint(accs[ni][2]);
            a[2] = __float_as_uint(accs[ni][1]);
            a[3] = __float_as_uint(accs[ni][3]);
            const int base = wn + ni * 8;
            const float* Vr0 = Vb + (base + 2 * tig) * FPADV;
            const float* Vr1 = Vr0 + FPADV;
#pragma unroll
            for (int nd = 0; nd < 16; ++nd) {
                const int c = nd * 8 + gid;
                uint32_t b[2];
                b[0] = *(const uint32_t*)&Vr0[c];
                b[1] = *(const uint32_t*)&Vr1[c];
                mma16n8k8(acc_o[nd], a, b);
            }
        }
    }

    // ---- cross-warp O + l reduction, finalize ----
    __syncthreads();       // KV smem dead; safe to reuse as slab
    if (wni == 1) {
#pragma unroll
        for (int nd = 0; nd < 16; ++nd) {
            const int d = nd * 8 + 2 * tig;
            *(float2*)&smf[OSLAB + row0 * FPADD + d] = make_float2(acc_o[nd][0], acc_o[nd][1]);
            *(float2*)&smf[OSLAB + row1 * FPADD + d] = make_float2(acc_o[nd][2], acc_o[nd][3]);
        }
        if (tig == 0) { smf[ORDL + row0] = l0; smf[ORDL + row1] = l1; }
    }
    __syncthreads();
    if (wni == 0) {
        const float inv0 = 1.f / (l0 + smf[ORDL + row0]);
        const float inv1 = 1.f / (l1 + smf[ORDL + row1]);
        const int bb = bh >> 4;
        const int h  = bh & 15;
        float* o0 = attn + ((size_t)(bb * SEQ + grow0)) * HIDDEN + h * HEAD_DIM;
        float* o1 = attn + ((size_t)(bb * SEQ + grow1)) * HIDDEN + h * HEAD_DIM;
#pragma unroll
        for (int nd = 0; nd < 16; ++nd) {
            const int d = nd * 8 + 2 * tig;
            float2 s0 = *(const float2*)&smf[OSLAB + row0 * FPADD + d];
            float2 s1 = *(const float2*)&smf[OSLAB + row1 * FPADD + d];
            float2 w0 = {to_tf32((acc_o[nd][0] + s0.x) * inv0),
                         to_tf32((acc_o[nd][1] + s0.y) * inv0)};
            float2 w1 = {to_tf32((acc_o[nd][2] + s1.x) * inv1),
                         to_tf32((acc_o[nd][3] + s1.y) * inv1)};
            *(float2*)(o0 + d) = w0;
            *(float2*)(o1 + d) = w1;
        }
    }
}

// ============================================================================
// host launcher
// ============================================================================
extern "C" void kernel_launch(void* const* d_in, const int* in_sizes, int n_in,
                              void* d_out, int out_size)
{
    const float* x   = (const float*)d_in[0];
    const float* pm  = (const float*)d_in[1];
    const float* pol = (const float*)d_in[2];
    const float* mw  = (const float*)d_in[3];
    const float* Wq  = (const float*)d_in[4];
    const float* Wk  = (const float*)d_in[5];
    const float* Wv  = (const float*)d_in[6];
    const float* Wo  = (const float*)d_in[7];
    const float* bo  = (const float*)d_in[8];
    float* out = (float*)d_out;

    float *gq, *gk, *gv, *ga, *gw, *gx;
    cudaGetSymbolAddress((void**)&gq, g_q);
    cudaGetSymbolAddress((void**)&gk, g_k);
    cudaGetSymbolAddress((void**)&gv, g_v);
    cudaGetSymbolAddress((void**)&ga, g_attn);
    cudaGetSymbolAddress((void**)&gw, g_wt);
    cudaGetSymbolAddress((void**)&gx, g_xc);

    cudaFuncSetAttribute(flash_kernel,
                         cudaFuncAttributeMaxDynamicSharedMemorySize, FLASH_SMEM);
    cudaFuncSetAttribute(gemm_mma_kernel,
                         cudaFuncAttributeMaxDynamicSharedMemorySize, GEMM_SMEM);

    float* wtq = gw;
    float* wtk = gw + (size_t)HIDDEN * HIDDEN;
    float* wtv = gw + 2 * (size_t)HIDDEN * HIDDEN;
    float* wto = gw + 3 * (size_t)HIDDEN * HIDDEN;

    const int n4 = HIDDEN * HIDDEN / 4;
    cvt_tf32_kernel<<<(n4 + 255) / 256, 256>>>(x, gx, n4);
    transpose2048<<<dim3(64, 64, 4), 256>>>(Wq, Wk, Wv, Wo, gw);

    // K1: QKV projections
    gemm_mma_kernel<<<dim3(HIDDEN / BN, MROWS / BM, 3), 128, GEMM_SMEM>>>(
        gx, wtq, wtk, wtv, gq, gk, gv, nullptr, 1);

    // K2: RoPE + tf32 rounding of k, v
    int rope_n = BATCH * HEADS * SEQ * 64;
    rope_kernel<<<(rope_n + 255) / 256, 256>>>(gq, gk, gv);

    // K3: tensor-core flash attention (register-resident P)
    dim3 gfl(SEQ / 64, BATCH * HEADS);
    flash_kernel<<<gfl, 256, FLASH_SMEM>>>(gq, gk, gv, pm, pol, mw, ga);

    // K4: output projection + bias
    gemm_mma_kernel<<<dim3(HIDDEN / BN, MROWS / BM, 1), 128, GEMM_SMEM>>>(
        ga, wto, wto, wto, out, out, out, bo, 0);
}